// round 1
// baseline (speedup 1.0000x reference)
#include <cuda_runtime.h>
#include <math.h>

#define Bsz 4
#define Ssz 512
#define Dsz 1024
#define Hsz 16
#define HDsz 64
#define Lsz 6
#define Fsz 4096
#define Vsz 32000
#define NTOK (Bsz*Ssz)

#define NEG_INF (-1.0f/0.0f)

// ---------------- scratch (no allocation allowed; __device__ globals) ----------------
__device__ float g_X[NTOK*Dsz];
__device__ float g_Q[NTOK*Dsz];
__device__ float g_K[NTOK*Dsz];
__device__ float g_V[NTOK*Dsz];
__device__ float g_CTX[NTOK*Dsz];
__device__ float g_T[NTOK*Dsz];
__device__ float g_FF[(size_t)NTOK*Fsz];
__device__ float g_SC[(size_t)Bsz*Hsz*Ssz*Ssz];

// ---------------- embedding * sqrt(D) + sinusoidal PE ----------------
__global__ void embed_kernel(const int* __restrict__ ids, const float* __restrict__ emb,
                             float* __restrict__ X)
{
    int row = blockIdx.x;          // token index 0..NTOK-1
    int s   = row % Ssz;           // position within sequence
    int id  = ids[row];
    const float* e = emb + (size_t)id * Dsz;
    float* x = X + (size_t)row * Dsz;
    const float nl = -logf(10000.0f) / (float)Dsz;
    for (int d = threadIdx.x; d < Dsz; d += blockDim.x) {
        int i = d >> 1;
        float div = expf((float)(2 * i) * nl);
        float ang = (float)s * div;
        float pe  = (d & 1) ? cosf(ang) : sinf(ang);
        x[d] = e[d] * 32.0f + pe;   // sqrt(1024) = 32
    }
}

// ---------------- generic tiled SGEMM: C = A[M,K] @ W[K,N] + bias, optional ReLU ----------------
// M % 64 == 0, N % 64 == 0, K % 16 == 0 (true for all shapes here)
#define BM 64
#define BN 64
#define BK 16
__global__ void sgemm_bias(const float* __restrict__ A, const float* __restrict__ W,
                           const float* __restrict__ bias, float* __restrict__ C,
                           int M, int N, int K, int relu)
{
    __shared__ float As[BK][BM + 1];
    __shared__ float Ws[BK][BN];
    int tid = threadIdx.x;
    int tx = tid & 15, ty = tid >> 4;
    int row0 = blockIdx.y * BM, col0 = blockIdx.x * BN;
    const float* Ap = A + (size_t)row0 * K;
    const float* Wp = W + col0;
    float acc[4][4] = {};
    for (int k0 = 0; k0 < K; k0 += BK) {
#pragma unroll
        for (int i = tid; i < BM * BK; i += 256) {
            int r = i >> 4, c = i & 15;
            As[c][r] = Ap[(size_t)r * K + k0 + c];
        }
#pragma unroll
        for (int i = tid; i < BK * BN; i += 256) {
            int r = i >> 6, c = i & 63;
            Ws[r][c] = Wp[(size_t)(k0 + r) * N + c];
        }
        __syncthreads();
#pragma unroll
        for (int kk = 0; kk < BK; kk++) {
            float a[4], w[4];
#pragma unroll
            for (int i = 0; i < 4; i++) a[i] = As[kk][ty * 4 + i];
#pragma unroll
            for (int j = 0; j < 4; j++) w[j] = Ws[kk][tx * 4 + j];
#pragma unroll
            for (int i = 0; i < 4; i++)
#pragma unroll
                for (int j = 0; j < 4; j++)
                    acc[i][j] = fmaf(a[i], w[j], acc[i][j]);
        }
        __syncthreads();
    }
#pragma unroll
    for (int i = 0; i < 4; i++) {
        int r = row0 + ty * 4 + i;
#pragma unroll
        for (int j = 0; j < 4; j++) {
            int c = col0 + tx * 4 + j;
            float v = acc[i][j] + bias[c];
            if (relu) v = fmaxf(v, 0.0f);
            C[(size_t)r * N + c] = v;
        }
    }
}

// ---------------- attention scores: SC[b,h,i,j] = (q.k)/8 + causal[i,j] + pad[j] ----------------
__global__ void attn_scores(const float* __restrict__ Q, const float* __restrict__ K,
                            const float* __restrict__ causal, const int* __restrict__ ids,
                            float* __restrict__ SC)
{
    int bh = blockIdx.z;
    int b = bh >> 4, h = bh & 15;
    int i0 = blockIdx.y * 64, j0 = blockIdx.x * 64;
    __shared__ float qs[HDsz][65];
    __shared__ float ks[HDsz][65];
    int tid = threadIdx.x, tx = tid & 15, ty = tid >> 4;
    const float* Qp = Q + ((size_t)(b * Ssz + i0)) * Dsz + h * HDsz;
    const float* Kp = K + ((size_t)(b * Ssz + j0)) * Dsz + h * HDsz;
#pragma unroll
    for (int i = tid; i < 64 * 64; i += 256) {
        int r = i >> 6, d = i & 63;
        qs[d][r] = Qp[(size_t)r * Dsz + d];
        ks[d][r] = Kp[(size_t)r * Dsz + d];
    }
    __syncthreads();
    float acc[4][4] = {};
#pragma unroll 8
    for (int d = 0; d < HDsz; d++) {
        float a[4], w[4];
#pragma unroll
        for (int i = 0; i < 4; i++) a[i] = qs[d][ty * 4 + i];
#pragma unroll
        for (int j = 0; j < 4; j++) w[j] = ks[d][tx * 4 + j];
#pragma unroll
        for (int i = 0; i < 4; i++)
#pragma unroll
            for (int j = 0; j < 4; j++)
                acc[i][j] = fmaf(a[i], w[j], acc[i][j]);
    }
    float* out = SC + (size_t)bh * Ssz * Ssz;
#pragma unroll
    for (int i = 0; i < 4; i++) {
        int ri = i0 + ty * 4 + i;
#pragma unroll
        for (int j = 0; j < 4; j++) {
            int cj = j0 + tx * 4 + j;
            float pad = (ids[b * Ssz + cj] == 0) ? NEG_INF : 0.0f;
            out[(size_t)ri * Ssz + cj] = acc[i][j] * 0.125f + causal[ri * Ssz + cj] + pad;
        }
    }
}

// ---------------- softmax over rows of length 512 (with all -inf -> uniform) ----------------
__global__ void softmax512(float* __restrict__ SC)
{
    float* p = SC + (size_t)blockIdx.x * Ssz;
    int t = threadIdx.x;
    float a = p[t], b2 = p[t + 256];
    __shared__ float red[256];
    red[t] = fmaxf(a, b2);
    __syncthreads();
    for (int s = 128; s > 0; s >>= 1) {
        if (t < s) red[t] = fmaxf(red[t], red[t + s]);
        __syncthreads();
    }
    float rmax = red[0];
    __syncthreads();
    if (rmax == NEG_INF) {          // whole row masked -> reference zeroes scores -> uniform
        p[t] = 1.0f / Ssz;
        p[t + 256] = 1.0f / Ssz;
        return;
    }
    float e0 = expf(a - rmax), e1 = expf(b2 - rmax);
    red[t] = e0 + e1;
    __syncthreads();
    for (int s = 128; s > 0; s >>= 1) {
        if (t < s) red[t] += red[t + s];
        __syncthreads();
    }
    float inv = 1.0f / red[0];
    p[t] = e0 * inv;
    p[t + 256] = e1 * inv;
}

// ---------------- ctx[b,i,h,:] = sum_j w[b,h,i,j] * v[b,j,h,:] ----------------
__global__ void attn_ctx(const float* __restrict__ SC, const float* __restrict__ V,
                         float* __restrict__ CTX)
{
    int bh = blockIdx.y;
    int b = bh >> 4, h = bh & 15;
    int i0 = blockIdx.x * 64;
    const float* W = SC + (size_t)bh * Ssz * Ssz;
    __shared__ float ws[16][65];
    __shared__ float vs[16][64];
    int tid = threadIdx.x, tx = tid & 15, ty = tid >> 4;
    float acc[4][4] = {};
    for (int j0 = 0; j0 < Ssz; j0 += 16) {
#pragma unroll
        for (int i = tid; i < 64 * 16; i += 256) {
            int r = i >> 4, c = i & 15;
            ws[c][r] = W[(size_t)(i0 + r) * Ssz + j0 + c];
        }
#pragma unroll
        for (int i = tid; i < 16 * 64; i += 256) {
            int c = i >> 6, n = i & 63;
            vs[c][n] = V[((size_t)(b * Ssz + j0 + c)) * Dsz + h * HDsz + n];
        }
        __syncthreads();
#pragma unroll
        for (int kk = 0; kk < 16; kk++) {
            float a[4], w[4];
#pragma unroll
            for (int i = 0; i < 4; i++) a[i] = ws[kk][ty * 4 + i];
#pragma unroll
            for (int j = 0; j < 4; j++) w[j] = vs[kk][tx * 4 + j];
#pragma unroll
            for (int i = 0; i < 4; i++)
#pragma unroll
                for (int j = 0; j < 4; j++)
                    acc[i][j] = fmaf(a[i], w[j], acc[i][j]);
        }
        __syncthreads();
    }
#pragma unroll
    for (int i = 0; i < 4; i++)
#pragma unroll
        for (int j = 0; j < 4; j++)
            CTX[((size_t)(b * Ssz + i0 + ty * 4 + i)) * Dsz + h * HDsz + tx * 4 + j] = acc[i][j];
}

// ---------------- X = LayerNorm(X + T) * g + b ----------------
__global__ void add_ln(const float* __restrict__ X, const float* __restrict__ T,
                       const float* __restrict__ g, const float* __restrict__ bb,
                       float* __restrict__ O)
{
    int row = blockIdx.x;
    int t = threadIdx.x;
    const float* x = X + (size_t)row * Dsz;
    const float* tt = T + (size_t)row * Dsz;
    float y[4];
    float s = 0.0f;
#pragma unroll
    for (int k = 0; k < 4; k++) {
        int d = t + k * 256;
        y[k] = x[d] + tt[d];
        s += y[k];
    }
    __shared__ float red[256];
    red[t] = s;
    __syncthreads();
    for (int st = 128; st > 0; st >>= 1) {
        if (t < st) red[t] += red[t + st];
        __syncthreads();
    }
    float mean = red[0] * (1.0f / Dsz);
    __syncthreads();
    float ss = 0.0f;
#pragma unroll
    for (int k = 0; k < 4; k++) {
        float d = y[k] - mean;
        ss += d * d;
    }
    red[t] = ss;
    __syncthreads();
    for (int st = 128; st > 0; st >>= 1) {
        if (t < st) red[t] += red[t + st];
        __syncthreads();
    }
    float var = red[0] * (1.0f / Dsz);
    float inv = rsqrtf(var + 1e-5f);
    float* o = O + (size_t)row * Dsz;
#pragma unroll
    for (int k = 0; k < 4; k++) {
        int d = t + k * 256;
        o[d] = (y[k] - mean) * inv * g[d] + bb[d];
    }
}

// ---------------- launch ----------------
extern "C" void kernel_launch(void* const* d_in, const int* in_sizes, int n_in,
                              void* d_out, int out_size)
{
    const int*   ids    = (const int*)  d_in[0];
    const float* causal = (const float*)d_in[1];
    const float* emb    = (const float*)d_in[2];
    const float* Wq     = (const float*)d_in[3];
    const float* bq     = (const float*)d_in[4];
    const float* Wk     = (const float*)d_in[5];
    const float* bk     = (const float*)d_in[6];
    const float* Wv     = (const float*)d_in[7];
    const float* bv     = (const float*)d_in[8];
    const float* Wo     = (const float*)d_in[9];
    const float* bo     = (const float*)d_in[10];
    const float* g1     = (const float*)d_in[11];
    const float* b1n    = (const float*)d_in[12];
    const float* W1     = (const float*)d_in[13];
    const float* b1f    = (const float*)d_in[14];
    const float* W2     = (const float*)d_in[15];
    const float* b2f    = (const float*)d_in[16];
    const float* g2     = (const float*)d_in[17];
    const float* b2n    = (const float*)d_in[18];
    const float* Wout   = (const float*)d_in[19];
    const float* bout   = (const float*)d_in[20];
    float* out = (float*)d_out;

    float *X, *Q, *K, *V, *CTX, *T, *FF, *SC;
    cudaGetSymbolAddress((void**)&X,   g_X);
    cudaGetSymbolAddress((void**)&Q,   g_Q);
    cudaGetSymbolAddress((void**)&K,   g_K);
    cudaGetSymbolAddress((void**)&V,   g_V);
    cudaGetSymbolAddress((void**)&CTX, g_CTX);
    cudaGetSymbolAddress((void**)&T,   g_T);
    cudaGetSymbolAddress((void**)&FF,  g_FF);
    cudaGetSymbolAddress((void**)&SC,  g_SC);

    embed_kernel<<<NTOK, 256>>>(ids, emb, X);

    for (int l = 0; l < Lsz; l++) {
        const float* wq = Wq + (size_t)l * Dsz * Dsz;
        const float* wk = Wk + (size_t)l * Dsz * Dsz;
        const float* wv = Wv + (size_t)l * Dsz * Dsz;
        const float* wo = Wo + (size_t)l * Dsz * Dsz;
        const float* w1 = W1 + (size_t)l * Dsz * Fsz;
        const float* w2 = W2 + (size_t)l * Fsz * Dsz;
        const float* bql = bq + (size_t)l * Dsz;
        const float* bkl = bk + (size_t)l * Dsz;
        const float* bvl = bv + (size_t)l * Dsz;
        const float* bol = bo + (size_t)l * Dsz;
        const float* b1fl = b1f + (size_t)l * Fsz;
        const float* b2fl = b2f + (size_t)l * Dsz;
        const float* g1l = g1 + (size_t)l * Dsz;
        const float* b1nl = b1n + (size_t)l * Dsz;
        const float* g2l = g2 + (size_t)l * Dsz;
        const float* b2nl = b2n + (size_t)l * Dsz;

        dim3 gDD(Dsz / BN, NTOK / BM);
        sgemm_bias<<<gDD, 256>>>(X, wq, bql, Q, NTOK, Dsz, Dsz, 0);
        sgemm_bias<<<gDD, 256>>>(X, wk, bkl, K, NTOK, Dsz, Dsz, 0);
        sgemm_bias<<<gDD, 256>>>(X, wv, bvl, V, NTOK, Dsz, Dsz, 0);

        attn_scores<<<dim3(Ssz / 64, Ssz / 64, Bsz * Hsz), 256>>>(Q, K, causal, ids, SC);
        softmax512<<<Bsz * Hsz * Ssz, 256>>>(SC);
        attn_ctx<<<dim3(Ssz / 64, Bsz * Hsz), 256>>>(SC, V, CTX);

        sgemm_bias<<<gDD, 256>>>(CTX, wo, bol, T, NTOK, Dsz, Dsz, 0);
        add_ln<<<NTOK, 256>>>(X, T, g1l, b1nl, X);

        sgemm_bias<<<dim3(Fsz / BN, NTOK / BM), 256>>>(X, w1, b1fl, FF, NTOK, Fsz, Dsz, 1);
        sgemm_bias<<<dim3(Dsz / BN, NTOK / BM), 256>>>(FF, w2, b2fl, T, NTOK, Dsz, Fsz, 0);
        add_ln<<<NTOK, 256>>>(X, T, g2l, b2nl, X);
    }

    sgemm_bias<<<dim3(Vsz / BN, NTOK / BM), 256>>>(X, Wout, bout, out, NTOK, Vsz, Dsz, 0);
}

// round 5
// speedup vs baseline: 2.3806x; 2.3806x over previous
#include <cuda_runtime.h>
#include <math.h>

#define Bsz 4
#define Ssz 512
#define Dsz 1024
#define Hsz 16
#define HDsz 64
#define Lsz 6
#define Fsz 4096
#define Vsz 32000
#define NTOK (Bsz*Ssz)

#define NEG_INF (-1.0f/0.0f)

// ---------------- scratch (no allocation allowed; __device__ globals) ----------------
__device__ float g_X[NTOK*Dsz];
__device__ float g_Q[NTOK*Dsz];
__device__ float g_K[NTOK*Dsz];
__device__ float g_V[NTOK*Dsz];
__device__ float g_CTX[NTOK*Dsz];
__device__ float g_T[NTOK*Dsz];
__device__ float g_FF[(size_t)NTOK*Fsz];
__device__ float g_SC[(size_t)Bsz*Hsz*Ssz*Ssz];

// ---------------- embedding * sqrt(D) + sinusoidal PE ----------------
__global__ void embed_kernel(const int* __restrict__ ids, const float* __restrict__ emb,
                             float* __restrict__ X)
{
    int row = blockIdx.x;
    int s   = row % Ssz;
    int id  = ids[row];
    const float* e = emb + (size_t)id * Dsz;
    float* x = X + (size_t)row * Dsz;
    const float nl = -logf(10000.0f) / (float)Dsz;
    for (int d = threadIdx.x; d < Dsz; d += blockDim.x) {
        int i = d >> 1;
        float div = expf((float)(2 * i) * nl);
        float ang = (float)s * div;
        float pe  = (d & 1) ? cosf(ang) : sinf(ang);
        x[d] = e[d] * 32.0f + pe;
    }
}

// ---------------- 128x128x8 double-buffered SGEMM, 8x8 microtile (4+4 split) ----------------
// C = A[M,K] @ W[K,N] + bias, optional ReLU. M%128==0, N%128==0, K%8==0.
#define BM 128
#define BN 128
#define BK 8

struct GemmArgs { const float* W; const float* bias; float* C; };

__device__ __forceinline__ void gemm_core(const float* __restrict__ A,
                                          const float* __restrict__ W,
                                          const float* __restrict__ bias,
                                          float* __restrict__ C,
                                          int M, int N, int K, int relu,
                                          int bx, int by)
{
    __shared__ float As[2][BK][BM];
    __shared__ float Ws[2][BK][BN];
    int tid = threadIdx.x;
    int tx = tid & 15, ty = tid >> 4;
    int row0 = by * BM, col0 = bx * BN;
    const float* Ap = A + (size_t)row0 * K;
    const float* Wp = W + col0;

    // global-load mapping
    int ar = tid >> 1;           // 0..127 (M within tile)
    int ac = (tid & 1) * 4;      // 0 or 4 (K within tile)
    int wr = tid >> 5;           // 0..7   (K within tile)
    int wc = (tid & 31) * 4;     // 0..124 (N within tile)

    float4 aReg = *(const float4*)(Ap + (size_t)ar * K + ac);
    float4 wReg = *(const float4*)(Wp + (size_t)wr * N + wc);
    As[0][ac + 0][ar] = aReg.x;
    As[0][ac + 1][ar] = aReg.y;
    As[0][ac + 2][ar] = aReg.z;
    As[0][ac + 3][ar] = aReg.w;
    *(float4*)&Ws[0][wr][wc] = wReg;
    __syncthreads();

    float acc[8][8] = {};
    int nk = K / BK;
    for (int kt = 0; kt < nk; kt++) {
        int cur = kt & 1, nxt = cur ^ 1;
        if (kt + 1 < nk) {
            int k0 = (kt + 1) * BK;
            aReg = *(const float4*)(Ap + (size_t)ar * K + k0 + ac);
            wReg = *(const float4*)(Wp + (size_t)(k0 + wr) * N + wc);
        }
#pragma unroll
        for (int kk = 0; kk < BK; kk++) {
            float a[8], w[8];
            *(float4*)(a)     = *(float4*)&As[cur][kk][ty * 4];
            *(float4*)(a + 4) = *(float4*)&As[cur][kk][64 + ty * 4];
            *(float4*)(w)     = *(float4*)&Ws[cur][kk][tx * 4];
            *(float4*)(w + 4) = *(float4*)&Ws[cur][kk][64 + tx * 4];
#pragma unroll
            for (int i = 0; i < 8; i++)
#pragma unroll
                for (int j = 0; j < 8; j++)
                    acc[i][j] = fmaf(a[i], w[j], acc[i][j]);
        }
        if (kt + 1 < nk) {
            As[nxt][ac + 0][ar] = aReg.x;
            As[nxt][ac + 1][ar] = aReg.y;
            As[nxt][ac + 2][ar] = aReg.z;
            As[nxt][ac + 3][ar] = aReg.w;
            *(float4*)&Ws[nxt][wr][wc] = wReg;
            __syncthreads();
        }
    }

    // epilogue: bias (+ReLU), float4 stores
    float4 b0 = *(const float4*)(bias + col0 + tx * 4);
    float4 b1 = *(const float4*)(bias + col0 + 64 + tx * 4);
#pragma unroll
    for (int i = 0; i < 8; i++) {
        int ri = row0 + ((i < 4) ? (ty * 4 + i) : (64 + ty * 4 + i - 4));
        float4 v0, v1;
        v0.x = acc[i][0] + b0.x; v0.y = acc[i][1] + b0.y;
        v0.z = acc[i][2] + b0.z; v0.w = acc[i][3] + b0.w;
        v1.x = acc[i][4] + b1.x; v1.y = acc[i][5] + b1.y;
        v1.z = acc[i][6] + b1.z; v1.w = acc[i][7] + b1.w;
        if (relu) {
            v0.x = fmaxf(v0.x, 0.f); v0.y = fmaxf(v0.y, 0.f);
            v0.z = fmaxf(v0.z, 0.f); v0.w = fmaxf(v0.w, 0.f);
            v1.x = fmaxf(v1.x, 0.f); v1.y = fmaxf(v1.y, 0.f);
            v1.z = fmaxf(v1.z, 0.f); v1.w = fmaxf(v1.w, 0.f);
        }
        *(float4*)(C + (size_t)ri * N + col0 + tx * 4)      = v0;
        *(float4*)(C + (size_t)ri * N + col0 + 64 + tx * 4) = v1;
    }
}

__global__ __launch_bounds__(256, 2)
void sgemm_bias(const float* __restrict__ A, const float* __restrict__ W,
                const float* __restrict__ bias, float* __restrict__ C,
                int M, int N, int K, int relu)
{
    gemm_core(A, W, bias, C, M, N, K, relu, blockIdx.x, blockIdx.y);
}

// batched QKV: same A, three weights/biases/outputs selected by blockIdx.z
__global__ __launch_bounds__(256, 2)
void sgemm_qkv(const float* __restrict__ A,
               const float* __restrict__ Wq, const float* __restrict__ bq, float* __restrict__ Q,
               const float* __restrict__ Wk, const float* __restrict__ bk, float* __restrict__ K_,
               const float* __restrict__ Wv, const float* __restrict__ bv, float* __restrict__ V)
{
    const float* W = (blockIdx.z == 0) ? Wq : (blockIdx.z == 1) ? Wk : Wv;
    const float* b = (blockIdx.z == 0) ? bq : (blockIdx.z == 1) ? bk : bv;
    float* C       = (blockIdx.z == 0) ? Q  : (blockIdx.z == 1) ? K_ : V;
    gemm_core(A, W, b, C, NTOK, Dsz, Dsz, 0, blockIdx.x, blockIdx.y);
}

// ---------------- attention scores: SC[b,h,i,j] = (q.k)/8 + causal[i,j] + pad[j] ----------------
__global__ void attn_scores(const float* __restrict__ Q, const float* __restrict__ K,
                            const float* __restrict__ causal, const int* __restrict__ ids,
                            float* __restrict__ SC)
{
    int bh = blockIdx.z;
    int b = bh >> 4, h = bh & 15;
    int i0 = blockIdx.y * 64, j0 = blockIdx.x * 64;
    __shared__ float qs[HDsz][65];
    __shared__ float ks[HDsz][65];
    int tid = threadIdx.x, tx = tid & 15, ty = tid >> 4;
    const float* Qp = Q + ((size_t)(b * Ssz + i0)) * Dsz + h * HDsz;
    const float* Kp = K + ((size_t)(b * Ssz + j0)) * Dsz + h * HDsz;
#pragma unroll
    for (int i = tid; i < 64 * 64; i += 256) {
        int r = i >> 6, d = i & 63;
        qs[d][r] = Qp[(size_t)r * Dsz + d];
        ks[d][r] = Kp[(size_t)r * Dsz + d];
    }
    __syncthreads();
    float acc[4][4] = {};
#pragma unroll 8
    for (int d = 0; d < HDsz; d++) {
        float a[4], w[4];
#pragma unroll
        for (int i = 0; i < 4; i++) a[i] = qs[d][ty * 4 + i];
#pragma unroll
        for (int j = 0; j < 4; j++) w[j] = ks[d][tx * 4 + j];
#pragma unroll
        for (int i = 0; i < 4; i++)
#pragma unroll
            for (int j = 0; j < 4; j++)
                acc[i][j] = fmaf(a[i], w[j], acc[i][j]);
    }
    float* out = SC + (size_t)bh * Ssz * Ssz;
#pragma unroll
    for (int i = 0; i < 4; i++) {
        int ri = i0 + ty * 4 + i;
#pragma unroll
        for (int j = 0; j < 4; j++) {
            int cj = j0 + tx * 4 + j;
            float pad = (ids[b * Ssz + cj] == 0) ? NEG_INF : 0.0f;
            out[(size_t)ri * Ssz + cj] = acc[i][j] * 0.125f + causal[ri * Ssz + cj] + pad;
        }
    }
}

// ---------------- softmax over rows of length 512 ----------------
__global__ void softmax512(float* __restrict__ SC)
{
    float* p = SC + (size_t)blockIdx.x * Ssz;
    int t = threadIdx.x;
    float a = p[t], b2 = p[t + 256];
    __shared__ float red[256];
    red[t] = fmaxf(a, b2);
    __syncthreads();
    for (int s = 128; s > 0; s >>= 1) {
        if (t < s) red[t] = fmaxf(red[t], red[t + s]);
        __syncthreads();
    }
    float rmax = red[0];
    __syncthreads();
    if (rmax == NEG_INF) {
        p[t] = 1.0f / Ssz;
        p[t + 256] = 1.0f / Ssz;
        return;
    }
    float e0 = expf(a - rmax), e1 = expf(b2 - rmax);
    red[t] = e0 + e1;
    __syncthreads();
    for (int s = 128; s > 0; s >>= 1) {
        if (t < s) red[t] += red[t + s];
        __syncthreads();
    }
    float inv = 1.0f / red[0];
    p[t] = e0 * inv;
    p[t + 256] = e1 * inv;
}

// ---------------- ctx[b,i,h,:] = sum_j w[b,h,i,j] * v[b,j,h,:] ----------------
__global__ void attn_ctx(const float* __restrict__ SC, const float* __restrict__ V,
                         float* __restrict__ CTX)
{
    int bh = blockIdx.y;
    int b = bh >> 4, h = bh & 15;
    int i0 = blockIdx.x * 64;
    const float* W = SC + (size_t)bh * Ssz * Ssz;
    __shared__ float ws[16][65];
    __shared__ float vs[16][64];
    int tid = threadIdx.x, tx = tid & 15, ty = tid >> 4;
    float acc[4][4] = {};
    for (int j0 = 0; j0 < Ssz; j0 += 16) {
#pragma unroll
        for (int i = tid; i < 64 * 16; i += 256) {
            int r = i >> 4, c = i & 15;
            ws[c][r] = W[(size_t)(i0 + r) * Ssz + j0 + c];
        }
#pragma unroll
        for (int i = tid; i < 16 * 64; i += 256) {
            int c = i >> 6, n = i & 63;
            vs[c][n] = V[((size_t)(b * Ssz + j0 + c)) * Dsz + h * HDsz + n];
        }
        __syncthreads();
#pragma unroll
        for (int kk = 0; kk < 16; kk++) {
            float a[4], w[4];
#pragma unroll
            for (int i = 0; i < 4; i++) a[i] = ws[kk][ty * 4 + i];
#pragma unroll
            for (int j = 0; j < 4; j++) w[j] = vs[kk][tx * 4 + j];
#pragma unroll
            for (int i = 0; i < 4; i++)
#pragma unroll
                for (int j = 0; j < 4; j++)
                    acc[i][j] = fmaf(a[i], w[j], acc[i][j]);
        }
        __syncthreads();
    }
#pragma unroll
    for (int i = 0; i < 4; i++)
#pragma unroll
        for (int j = 0; j < 4; j++)
            CTX[((size_t)(b * Ssz + i0 + ty * 4 + i)) * Dsz + h * HDsz + tx * 4 + j] = acc[i][j];
}

// ---------------- X = LayerNorm(X + T) * g + b ----------------
__global__ void add_ln(const float* __restrict__ X, const float* __restrict__ T,
                       const float* __restrict__ g, const float* __restrict__ bb,
                       float* __restrict__ O)
{
    int row = blockIdx.x;
    int t = threadIdx.x;
    const float* x = X + (size_t)row * Dsz;
    const float* tt = T + (size_t)row * Dsz;
    float y[4];
    float s = 0.0f;
#pragma unroll
    for (int k = 0; k < 4; k++) {
        int d = t + k * 256;
        y[k] = x[d] + tt[d];
        s += y[k];
    }
    __shared__ float red[256];
    red[t] = s;
    __syncthreads();
    for (int st = 128; st > 0; st >>= 1) {
        if (t < st) red[t] += red[t + st];
        __syncthreads();
    }
    float mean = red[0] * (1.0f / Dsz);
    __syncthreads();
    float ss = 0.0f;
#pragma unroll
    for (int k = 0; k < 4; k++) {
        float d = y[k] - mean;
        ss += d * d;
    }
    red[t] = ss;
    __syncthreads();
    for (int st = 128; st > 0; st >>= 1) {
        if (t < st) red[t] += red[t + st];
        __syncthreads();
    }
    float var = red[0] * (1.0f / Dsz);
    float inv = rsqrtf(var + 1e-5f);
    float* o = O + (size_t)row * Dsz;
#pragma unroll
    for (int k = 0; k < 4; k++) {
        int d = t + k * 256;
        o[d] = (y[k] - mean) * inv * g[d] + bb[d];
    }
}

// ---------------- launch ----------------
extern "C" void kernel_launch(void* const* d_in, const int* in_sizes, int n_in,
                              void* d_out, int out_size)
{
    const int*   ids    = (const int*)  d_in[0];
    const float* causal = (const float*)d_in[1];
    const float* emb    = (const float*)d_in[2];
    const float* Wq     = (const float*)d_in[3];
    const float* bq     = (const float*)d_in[4];
    const float* Wk     = (const float*)d_in[5];
    const float* bk     = (const float*)d_in[6];
    const float* Wv     = (const float*)d_in[7];
    const float* bv     = (const float*)d_in[8];
    const float* Wo     = (const float*)d_in[9];
    const float* bo     = (const float*)d_in[10];
    const float* g1     = (const float*)d_in[11];
    const float* b1n    = (const float*)d_in[12];
    const float* W1     = (const float*)d_in[13];
    const float* b1f    = (const float*)d_in[14];
    const float* W2     = (const float*)d_in[15];
    const float* b2f    = (const float*)d_in[16];
    const float* g2     = (const float*)d_in[17];
    const float* b2n    = (const float*)d_in[18];
    const float* Wout   = (const float*)d_in[19];
    const float* bout   = (const float*)d_in[20];
    float* out = (float*)d_out;

    float *X, *Q, *K, *V, *CTX, *T, *FF, *SC;
    cudaGetSymbolAddress((void**)&X,   g_X);
    cudaGetSymbolAddress((void**)&Q,   g_Q);
    cudaGetSymbolAddress((void**)&K,   g_K);
    cudaGetSymbolAddress((void**)&V,   g_V);
    cudaGetSymbolAddress((void**)&CTX, g_CTX);
    cudaGetSymbolAddress((void**)&T,   g_T);
    cudaGetSymbolAddress((void**)&FF,  g_FF);
    cudaGetSymbolAddress((void**)&SC,  g_SC);

    embed_kernel<<<NTOK, 256>>>(ids, emb, X);

    dim3 gDD(Dsz / BN, NTOK / BM);          // 8 x 16
    dim3 gQKV(Dsz / BN, NTOK / BM, 3);      // 8 x 16 x 3
    dim3 gDF(Fsz / BN, NTOK / BM);          // 32 x 16
    dim3 gV(Vsz / BN, NTOK / BM);           // 250 x 16

    for (int l = 0; l < Lsz; l++) {
        const float* wq = Wq + (size_t)l * Dsz * Dsz;
        const float* wk = Wk + (size_t)l * Dsz * Dsz;
        const float* wv = Wv + (size_t)l * Dsz * Dsz;
        const float* wo = Wo + (size_t)l * Dsz * Dsz;
        const float* w1 = W1 + (size_t)l * Dsz * Fsz;
        const float* w2 = W2 + (size_t)l * Fsz * Dsz;
        const float* bql = bq + (size_t)l * Dsz;
        const float* bkl = bk + (size_t)l * Dsz;
        const float* bvl = bv + (size_t)l * Dsz;
        const float* bol = bo + (size_t)l * Dsz;
        const float* b1fl = b1f + (size_t)l * Fsz;
        const float* b2fl = b2f + (size_t)l * Dsz;
        const float* g1l = g1 + (size_t)l * Dsz;
        const float* b1nl = b1n + (size_t)l * Dsz;
        const float* g2l = g2 + (size_t)l * Dsz;
        const float* b2nl = b2n + (size_t)l * Dsz;

        sgemm_qkv<<<gQKV, 256>>>(X, wq, bql, Q, wk, bkl, K, wv, bvl, V);

        attn_scores<<<dim3(Ssz / 64, Ssz / 64, Bsz * Hsz), 256>>>(Q, K, causal, ids, SC);
        softmax512<<<Bsz * Hsz * Ssz, 256>>>(SC);
        attn_ctx<<<dim3(Ssz / 64, Bsz * Hsz), 256>>>(SC, V, CTX);

        sgemm_bias<<<gDD, 256>>>(CTX, wo, bol, T, NTOK, Dsz, Dsz, 0);
        add_ln<<<NTOK, 256>>>(X, T, g1l, b1nl, X);

        sgemm_bias<<<gDF, 256>>>(X, w1, b1fl, FF, NTOK, Fsz, Dsz, 1);
        sgemm_bias<<<gDD, 256>>>(FF, w2, b2fl, T, NTOK, Dsz, Fsz, 0);
        add_ln<<<NTOK, 256>>>(X, T, g2l, b2nl, X);
    }

    sgemm_bias<<<gV, 256>>>(X, Wout, bout, out, NTOK, Vsz, Dsz, 0);
}

// round 7
// speedup vs baseline: 2.6211x; 1.1011x over previous
#include <cuda_runtime.h>
#include <cstdint>
#include <math.h>

#define Bsz 4
#define Ssz 512
#define Dsz 1024
#define Hsz 16
#define HDsz 64
#define Lsz 6
#define Fsz 4096
#define Vsz 32000
#define NTOK (Bsz*Ssz)

#define NEG_INF (-1.0f/0.0f)

// ---------------- scratch (no allocation allowed; __device__ globals) ----------------
__device__ float g_X[NTOK*Dsz];
__device__ float g_Q[NTOK*Dsz];
__device__ float g_K[NTOK*Dsz];
__device__ float g_V[NTOK*Dsz];
__device__ float g_CTX[NTOK*Dsz];
__device__ float g_T[NTOK*Dsz];
__device__ float g_FF[(size_t)NTOK*Fsz];
__device__ float g_SC[(size_t)Bsz*Hsz*Ssz*Ssz];
// transposed (tf32-rounded) weights
__device__ float g_WTq[(size_t)Lsz*Dsz*Dsz];
__device__ float g_WTk[(size_t)Lsz*Dsz*Dsz];
__device__ float g_WTv[(size_t)Lsz*Dsz*Dsz];
__device__ float g_WTo[(size_t)Lsz*Dsz*Dsz];
__device__ float g_WT1[(size_t)Lsz*Dsz*Fsz];
__device__ float g_WT2[(size_t)Lsz*Fsz*Dsz];
__device__ float g_WTout[(size_t)Vsz*Dsz];

// ================= weight transpose (+ tf32 rounding) =================
// in: [K,N] row-major; out: [N,K] row-major; blockIdx.z = matrix index (layer)
__global__ void transpose_tf32(const float* __restrict__ in, float* __restrict__ out,
                               int K, int N)
{
    __shared__ float tile[32][33];
    size_t off = (size_t)blockIdx.z * K * N;
    in += off; out += off;
    int tx = threadIdx.x, ty = threadIdx.y;
    int n = blockIdx.x * 32 + tx;
    int k0 = blockIdx.y * 32;
#pragma unroll
    for (int i = ty; i < 32; i += 8)
        tile[i][tx] = in[(size_t)(k0 + i) * N + n];
    __syncthreads();
    int k = k0 + tx;
    int n0 = blockIdx.x * 32;
#pragma unroll
    for (int i = ty; i < 32; i += 8) {
        float v = tile[tx][i];
        asm("cvt.rna.tf32.f32 %0, %0;" : "+f"(v));
        out[(size_t)(n0 + i) * K + k] = v;
    }
}

// ================= tf32 mma.sync GEMM: C = A[M,K] @ WT[N,K]^T + bias =================
// CTA tile 128x128, K chunk 32, 8 warps (2m x 4n), warp tile 64x32 of m16n8k8.
// SMEM row pitch 36 floats -> fragment LDS hits bank==lane (conflict-free).
#define GPAD 36
#define GEMM_SMEM (4*128*GPAD*4)

__device__ __forceinline__ void mma_tf32(float* d, const uint32_t* a, const uint32_t* b)
{
    asm volatile("mma.sync.aligned.m16n8k8.row.col.f32.tf32.tf32.f32 "
        "{%0,%1,%2,%3}, {%4,%5,%6,%7}, {%8,%9}, {%0,%1,%2,%3};"
        : "+f"(d[0]), "+f"(d[1]), "+f"(d[2]), "+f"(d[3])
        : "r"(a[0]), "r"(a[1]), "r"(a[2]), "r"(a[3]), "r"(b[0]), "r"(b[1]));
}

__device__ __forceinline__ void gemm_mma_core(const float* __restrict__ A,
        const float* __restrict__ WT, const float* __restrict__ bias,
        float* __restrict__ C, int N, int K, int relu, int bx, int by)
{
    extern __shared__ float sm[];
    float* Abuf[2] = { sm,                sm + 2 * 128 * GPAD };
    float* Bbuf[2] = { sm + 128 * GPAD,   sm + 3 * 128 * GPAD };

    int tid = threadIdx.x, lane = tid & 31, wid = tid >> 5;
    int m0 = (wid & 1) * 64;      // warp m-offset within tile
    int n0 = (wid >> 1) * 32;     // warp n-offset within tile

    const float* Ap = A  + (size_t)(by * 128) * K;
    const float* Bp = WT + (size_t)(bx * 128) * K;

    int gr = tid >> 3;            // 0..31
    int gc = (tid & 7) * 4;       // 0..28

    float4 av[4], bv[4];
#pragma unroll
    for (int i = 0; i < 4; i++) {
        av[i] = *(const float4*)(Ap + (size_t)(gr + 32 * i) * K + gc);
        bv[i] = *(const float4*)(Bp + (size_t)(gr + 32 * i) * K + gc);
        asm("cvt.rna.tf32.f32 %0, %0;" : "+f"(av[i].x));
        asm("cvt.rna.tf32.f32 %0, %0;" : "+f"(av[i].y));
        asm("cvt.rna.tf32.f32 %0, %0;" : "+f"(av[i].z));
        asm("cvt.rna.tf32.f32 %0, %0;" : "+f"(av[i].w));
    }
#pragma unroll
    for (int i = 0; i < 4; i++) {
        *(float4*)&Abuf[0][(gr + 32 * i) * GPAD + gc] = av[i];
        *(float4*)&Bbuf[0][(gr + 32 * i) * GPAD + gc] = bv[i];
    }
    __syncthreads();

    float acc[4][4][4] = {};
    int lg = lane >> 2;           // 0..7 group id
    int lt = lane & 3;            // 0..3 thread-in-group

    int nch = K >> 5;
    for (int kt = 0; kt < nch; kt++) {
        int cur = kt & 1, nxt = cur ^ 1;
        if (kt + 1 < nch) {
            int k0 = (kt + 1) << 5;
#pragma unroll
            for (int i = 0; i < 4; i++) {
                av[i] = *(const float4*)(Ap + (size_t)(gr + 32 * i) * K + k0 + gc);
                bv[i] = *(const float4*)(Bp + (size_t)(gr + 32 * i) * K + k0 + gc);
                asm("cvt.rna.tf32.f32 %0, %0;" : "+f"(av[i].x));
                asm("cvt.rna.tf32.f32 %0, %0;" : "+f"(av[i].y));
                asm("cvt.rna.tf32.f32 %0, %0;" : "+f"(av[i].z));
                asm("cvt.rna.tf32.f32 %0, %0;" : "+f"(av[i].w));
            }
        }
        const float* As = Abuf[cur];
        const float* Bs = Bbuf[cur];
#pragma unroll
        for (int ks = 0; ks < 4; ks++) {
            int kk = ks * 8 + lt;
            uint32_t bfr[4][2];
#pragma unroll
            for (int nt = 0; nt < 4; nt++) {
                int n = n0 + nt * 8 + lg;
                bfr[nt][0] = __float_as_uint(Bs[n * GPAD + kk]);
                bfr[nt][1] = __float_as_uint(Bs[n * GPAD + kk + 4]);
            }
#pragma unroll
            for (int mt = 0; mt < 4; mt++) {
                int r = m0 + mt * 16 + lg;
                uint32_t afr[4];
                afr[0] = __float_as_uint(As[r * GPAD + kk]);
                afr[1] = __float_as_uint(As[(r + 8) * GPAD + kk]);
                afr[2] = __float_as_uint(As[r * GPAD + kk + 4]);
                afr[3] = __float_as_uint(As[(r + 8) * GPAD + kk + 4]);
#pragma unroll
                for (int nt = 0; nt < 4; nt++)
                    mma_tf32(acc[mt][nt], afr, bfr[nt]);
            }
        }
        if (kt + 1 < nch) {
            __syncthreads();
#pragma unroll
            for (int i = 0; i < 4; i++) {
                *(float4*)&Abuf[nxt][(gr + 32 * i) * GPAD + gc] = av[i];
                *(float4*)&Bbuf[nxt][(gr + 32 * i) * GPAD + gc] = bv[i];
            }
            __syncthreads();
        }
    }

    // epilogue: c0,c1 at (row=lg, col=lt*2,+1); c2,c3 at (row=lg+8)
#pragma unroll
    for (int mt = 0; mt < 4; mt++) {
        int r1 = by * 128 + m0 + mt * 16 + lg;
#pragma unroll
        for (int nt = 0; nt < 4; nt++) {
            int cb = bx * 128 + n0 + nt * 8 + lt * 2;
            float2 bb = *(const float2*)(bias + cb);
            float2 v0, v1;
            v0.x = acc[mt][nt][0] + bb.x; v0.y = acc[mt][nt][1] + bb.y;
            v1.x = acc[mt][nt][2] + bb.x; v1.y = acc[mt][nt][3] + bb.y;
            if (relu) {
                v0.x = fmaxf(v0.x, 0.f); v0.y = fmaxf(v0.y, 0.f);
                v1.x = fmaxf(v1.x, 0.f); v1.y = fmaxf(v1.y, 0.f);
            }
            *(float2*)(C + (size_t)r1 * N + cb)       = v0;
            *(float2*)(C + (size_t)(r1 + 8) * N + cb) = v1;
        }
    }
}

// grid: (M/128, N/128); blockIdx.x = m-block, blockIdx.y = n-block
__global__ __launch_bounds__(256)
void gemm_mma(const float* __restrict__ A, const float* __restrict__ WT,
              const float* __restrict__ bias, float* __restrict__ C,
              int N, int K, int relu)
{
    gemm_mma_core(A, WT, bias, C, N, K, relu, blockIdx.y, blockIdx.x);
}

__global__ __launch_bounds__(256)
void gemm_mma_qkv(const float* __restrict__ A,
                  const float* __restrict__ WTq, const float* __restrict__ bq, float* __restrict__ Q,
                  const float* __restrict__ WTk, const float* __restrict__ bk, float* __restrict__ Kp,
                  const float* __restrict__ WTv, const float* __restrict__ bv, float* __restrict__ V)
{
    const float* W = (blockIdx.z == 0) ? WTq : (blockIdx.z == 1) ? WTk : WTv;
    const float* b = (blockIdx.z == 0) ? bq  : (blockIdx.z == 1) ? bk  : bv;
    float* C       = (blockIdx.z == 0) ? Q   : (blockIdx.z == 1) ? Kp  : V;
    gemm_mma_core(A, W, b, C, Dsz, Dsz, 0, blockIdx.y, blockIdx.x);
}

// ---------------- embedding * sqrt(D) + sinusoidal PE ----------------
__global__ void embed_kernel(const int* __restrict__ ids, const float* __restrict__ emb,
                             float* __restrict__ X)
{
    int row = blockIdx.x;
    int s   = row % Ssz;
    int id  = ids[row];
    const float* e = emb + (size_t)id * Dsz;
    float* x = X + (size_t)row * Dsz;
    const float nl = -logf(10000.0f) / (float)Dsz;
    for (int d = threadIdx.x; d < Dsz; d += blockDim.x) {
        int i = d >> 1;
        float div = expf((float)(2 * i) * nl);
        float ang = (float)s * div;
        float pe  = (d & 1) ? cosf(ang) : sinf(ang);
        x[d] = e[d] * 32.0f + pe;
    }
}

// ---------------- attention scores ----------------
__global__ void attn_scores(const float* __restrict__ Q, const float* __restrict__ K,
                            const float* __restrict__ causal, const int* __restrict__ ids,
                            float* __restrict__ SC)
{
    int bh = blockIdx.z;
    int b = bh >> 4, h = bh & 15;
    int i0 = blockIdx.y * 64, j0 = blockIdx.x * 64;
    __shared__ float qs[HDsz][65];
    __shared__ float ks[HDsz][65];
    int tid = threadIdx.x, tx = tid & 15, ty = tid >> 4;
    const float* Qp = Q + ((size_t)(b * Ssz + i0)) * Dsz + h * HDsz;
    const float* Kp = K + ((size_t)(b * Ssz + j0)) * Dsz + h * HDsz;
#pragma unroll
    for (int i = tid; i < 64 * 64; i += 256) {
        int r = i >> 6, d = i & 63;
        qs[d][r] = Qp[(size_t)r * Dsz + d];
        ks[d][r] = Kp[(size_t)r * Dsz + d];
    }
    __syncthreads();
    float acc[4][4] = {};
#pragma unroll 8
    for (int d = 0; d < HDsz; d++) {
        float a[4], w[4];
#pragma unroll
        for (int i = 0; i < 4; i++) a[i] = qs[d][ty * 4 + i];
#pragma unroll
        for (int j = 0; j < 4; j++) w[j] = ks[d][tx * 4 + j];
#pragma unroll
        for (int i = 0; i < 4; i++)
#pragma unroll
            for (int j = 0; j < 4; j++)
                acc[i][j] = fmaf(a[i], w[j], acc[i][j]);
    }
    float* out = SC + (size_t)bh * Ssz * Ssz;
#pragma unroll
    for (int i = 0; i < 4; i++) {
        int ri = i0 + ty * 4 + i;
#pragma unroll
        for (int j = 0; j < 4; j++) {
            int cj = j0 + tx * 4 + j;
            float pad = (ids[b * Ssz + cj] == 0) ? NEG_INF : 0.0f;
            out[(size_t)ri * Ssz + cj] = acc[i][j] * 0.125f + causal[ri * Ssz + cj] + pad;
        }
    }
}

// ---------------- softmax over rows of length 512 ----------------
__global__ void softmax512(float* __restrict__ SC)
{
    float* p = SC + (size_t)blockIdx.x * Ssz;
    int t = threadIdx.x;
    float a = p[t], b2 = p[t + 256];
    __shared__ float red[256];
    red[t] = fmaxf(a, b2);
    __syncthreads();
    for (int s = 128; s > 0; s >>= 1) {
        if (t < s) red[t] = fmaxf(red[t], red[t + s]);
        __syncthreads();
    }
    float rmax = red[0];
    __syncthreads();
    if (rmax == NEG_INF) {
        p[t] = 1.0f / Ssz;
        p[t + 256] = 1.0f / Ssz;
        return;
    }
    float e0 = expf(a - rmax), e1 = expf(b2 - rmax);
    red[t] = e0 + e1;
    __syncthreads();
    for (int s = 128; s > 0; s >>= 1) {
        if (t < s) red[t] += red[t + s];
        __syncthreads();
    }
    float inv = 1.0f / red[0];
    p[t] = e0 * inv;
    p[t + 256] = e1 * inv;
}

// ---------------- ctx = softmax(scores) @ V ----------------
__global__ void attn_ctx(const float* __restrict__ SC, const float* __restrict__ V,
                         float* __restrict__ CTX)
{
    int bh = blockIdx.y;
    int b = bh >> 4, h = bh & 15;
    int i0 = blockIdx.x * 64;
    const float* W = SC + (size_t)bh * Ssz * Ssz;
    __shared__ float ws[16][65];
    __shared__ float vs[16][64];
    int tid = threadIdx.x, tx = tid & 15, ty = tid >> 4;
    float acc[4][4] = {};
    for (int j0 = 0; j0 < Ssz; j0 += 16) {
#pragma unroll
        for (int i = tid; i < 64 * 16; i += 256) {
            int r = i >> 4, c = i & 15;
            ws[c][r] = W[(size_t)(i0 + r) * Ssz + j0 + c];
        }
#pragma unroll
        for (int i = tid; i < 16 * 64; i += 256) {
            int c = i >> 6, n = i & 63;
            vs[c][n] = V[((size_t)(b * Ssz + j0 + c)) * Dsz + h * HDsz + n];
        }
        __syncthreads();
#pragma unroll
        for (int kk = 0; kk < 16; kk++) {
            float a[4], w[4];
#pragma unroll
            for (int i = 0; i < 4; i++) a[i] = ws[kk][ty * 4 + i];
#pragma unroll
            for (int j = 0; j < 4; j++) w[j] = vs[kk][tx * 4 + j];
#pragma unroll
            for (int i = 0; i < 4; i++)
#pragma unroll
                for (int j = 0; j < 4; j++)
                    acc[i][j] = fmaf(a[i], w[j], acc[i][j]);
        }
        __syncthreads();
    }
#pragma unroll
    for (int i = 0; i < 4; i++)
#pragma unroll
        for (int j = 0; j < 4; j++)
            CTX[((size_t)(b * Ssz + i0 + ty * 4 + i)) * Dsz + h * HDsz + tx * 4 + j] = acc[i][j];
}

// ---------------- X = LayerNorm(X + T) * g + b ----------------
__global__ void add_ln(const float* __restrict__ X, const float* __restrict__ T,
                       const float* __restrict__ g, const float* __restrict__ bb,
                       float* __restrict__ O)
{
    int row = blockIdx.x;
    int t = threadIdx.x;
    const float* x = X + (size_t)row * Dsz;
    const float* tt = T + (size_t)row * Dsz;
    float y[4];
    float s = 0.0f;
#pragma unroll
    for (int k = 0; k < 4; k++) {
        int d = t + k * 256;
        y[k] = x[d] + tt[d];
        s += y[k];
    }
    __shared__ float red[256];
    red[t] = s;
    __syncthreads();
    for (int st = 128; st > 0; st >>= 1) {
        if (t < st) red[t] += red[t + st];
        __syncthreads();
    }
    float mean = red[0] * (1.0f / Dsz);
    __syncthreads();
    float ss = 0.0f;
#pragma unroll
    for (int k = 0; k < 4; k++) {
        float d = y[k] - mean;
        ss += d * d;
    }
    red[t] = ss;
    __syncthreads();
    for (int st = 128; st > 0; st >>= 1) {
        if (t < st) red[t] += red[t + st];
        __syncthreads();
    }
    float var = red[0] * (1.0f / Dsz);
    float inv = rsqrtf(var + 1e-5f);
    float* o = O + (size_t)row * Dsz;
#pragma unroll
    for (int k = 0; k < 4; k++) {
        int d = t + k * 256;
        o[d] = (y[k] - mean) * inv * g[d] + bb[d];
    }
}

// ---------------- launch ----------------
extern "C" void kernel_launch(void* const* d_in, const int* in_sizes, int n_in,
                              void* d_out, int out_size)
{
    const int*   ids    = (const int*)  d_in[0];
    const float* causal = (const float*)d_in[1];
    const float* emb    = (const float*)d_in[2];
    const float* Wq     = (const float*)d_in[3];
    const float* bq     = (const float*)d_in[4];
    const float* Wk     = (const float*)d_in[5];
    const float* bk     = (const float*)d_in[6];
    const float* Wv     = (const float*)d_in[7];
    const float* bv     = (const float*)d_in[8];
    const float* Wo     = (const float*)d_in[9];
    const float* bo     = (const float*)d_in[10];
    const float* g1     = (const float*)d_in[11];
    const float* b1n    = (const float*)d_in[12];
    const float* W1     = (const float*)d_in[13];
    const float* b1f    = (const float*)d_in[14];
    const float* W2     = (const float*)d_in[15];
    const float* b2f    = (const float*)d_in[16];
    const float* g2     = (const float*)d_in[17];
    const float* b2n    = (const float*)d_in[18];
    const float* Wout   = (const float*)d_in[19];
    const float* bout   = (const float*)d_in[20];
    float* out = (float*)d_out;

    float *X, *Q, *K, *V, *CTX, *T, *FF, *SC;
    float *WTq, *WTk, *WTv, *WTo, *WT1, *WT2, *WTout;
    cudaGetSymbolAddress((void**)&X,   g_X);
    cudaGetSymbolAddress((void**)&Q,   g_Q);
    cudaGetSymbolAddress((void**)&K,   g_K);
    cudaGetSymbolAddress((void**)&V,   g_V);
    cudaGetSymbolAddress((void**)&CTX, g_CTX);
    cudaGetSymbolAddress((void**)&T,   g_T);
    cudaGetSymbolAddress((void**)&FF,  g_FF);
    cudaGetSymbolAddress((void**)&SC,  g_SC);
    cudaGetSymbolAddress((void**)&WTq, g_WTq);
    cudaGetSymbolAddress((void**)&WTk, g_WTk);
    cudaGetSymbolAddress((void**)&WTv, g_WTv);
    cudaGetSymbolAddress((void**)&WTo, g_WTo);
    cudaGetSymbolAddress((void**)&WT1, g_WT1);
    cudaGetSymbolAddress((void**)&WT2, g_WT2);
    cudaGetSymbolAddress((void**)&WTout, g_WTout);

    cudaFuncSetAttribute(gemm_mma,     cudaFuncAttributeMaxDynamicSharedMemorySize, GEMM_SMEM);
    cudaFuncSetAttribute(gemm_mma_qkv, cudaFuncAttributeMaxDynamicSharedMemorySize, GEMM_SMEM);

    // weight transposes (+tf32 rounding), recomputed every replay (deterministic)
    transpose_tf32<<<dim3(Dsz/32, Dsz/32, Lsz), dim3(32, 8)>>>(Wq, WTq, Dsz, Dsz);
    transpose_tf32<<<dim3(Dsz/32, Dsz/32, Lsz), dim3(32, 8)>>>(Wk, WTk, Dsz, Dsz);
    transpose_tf32<<<dim3(Dsz/32, Dsz/32, Lsz), dim3(32, 8)>>>(Wv, WTv, Dsz, Dsz);
    transpose_tf32<<<dim3(Dsz/32, Dsz/32, Lsz), dim3(32, 8)>>>(Wo, WTo, Dsz, Dsz);
    transpose_tf32<<<dim3(Fsz/32, Dsz/32, Lsz), dim3(32, 8)>>>(W1, WT1, Dsz, Fsz);
    transpose_tf32<<<dim3(Dsz/32, Fsz/32, Lsz), dim3(32, 8)>>>(W2, WT2, Fsz, Dsz);
    transpose_tf32<<<dim3(Vsz/32, Dsz/32, 1),   dim3(32, 8)>>>(Wout, WTout, Dsz, Vsz);

    embed_kernel<<<NTOK, 256>>>(ids, emb, X);

    for (int l = 0; l < Lsz; l++) {
        const float* wtq = WTq + (size_t)l * Dsz * Dsz;
        const float* wtk = WTk + (size_t)l * Dsz * Dsz;
        const float* wtv = WTv + (size_t)l * Dsz * Dsz;
        const float* wto = WTo + (size_t)l * Dsz * Dsz;
        const float* wt1 = WT1 + (size_t)l * Dsz * Fsz;
        const float* wt2 = WT2 + (size_t)l * Fsz * Dsz;
        const float* bql = bq + (size_t)l * Dsz;
        const float* bkl = bk + (size_t)l * Dsz;
        const float* bvl = bv + (size_t)l * Dsz;
        const float* bol = bo + (size_t)l * Dsz;
        const float* b1fl = b1f + (size_t)l * Fsz;
        const float* b2fl = b2f + (size_t)l * Dsz;
        const float* g1l = g1 + (size_t)l * Dsz;
        const float* b1nl = b1n + (size_t)l * Dsz;
        const float* g2l = g2 + (size_t)l * Dsz;
        const float* b2nl = b2n + (size_t)l * Dsz;

        gemm_mma_qkv<<<dim3(NTOK/128, Dsz/128, 3), 256, GEMM_SMEM>>>(
            X, wtq, bql, Q, wtk, bkl, K, wtv, bvl, V);

        attn_scores<<<dim3(Ssz/64, Ssz/64, Bsz*Hsz), 256>>>(Q, K, causal, ids, SC);
        softmax512<<<Bsz*Hsz*Ssz, 256>>>(SC);
        attn_ctx<<<dim3(Ssz/64, Bsz*Hsz), 256>>>(SC, V, CTX);

        gemm_mma<<<dim3(NTOK/128, Dsz/128), 256, GEMM_SMEM>>>(CTX, wto, bol, T, Dsz, Dsz, 0);
        add_ln<<<NTOK, 256>>>(X, T, g1l, b1nl, X);

        gemm_mma<<<dim3(NTOK/128, Fsz/128), 256, GEMM_SMEM>>>(X, wt1, b1fl, FF, Fsz, Dsz, 1);
        gemm_mma<<<dim3(NTOK/128, Dsz/128), 256, GEMM_SMEM>>>(FF, wt2, b2fl, T, Dsz, Fsz, 0);
        add_ln<<<NTOK, 256>>>(X, T, g2l, b2nl, X);
    }

    gemm_mma<<<dim3(NTOK/128, Vsz/128), 256, GEMM_SMEM>>>(X, WTout, bout, out, Vsz, Dsz, 0);
}

// round 8
// speedup vs baseline: 4.7123x; 1.7978x over previous
#include <cuda_runtime.h>
#include <cstdint>
#include <math.h>

#define Bsz 4
#define Ssz 512
#define Dsz 1024
#define Hsz 16
#define HDsz 64
#define Lsz 6
#define Fsz 4096
#define Vsz 32000
#define NTOK (Bsz*Ssz)

#define NEG_INF (-1.0f/0.0f)

// ---------------- scratch (no allocation allowed; __device__ globals) ----------------
__device__ float g_X[NTOK*Dsz];
__device__ float g_Q[NTOK*Dsz];
__device__ float g_K[NTOK*Dsz];
__device__ float g_V[NTOK*Dsz];
__device__ float g_CTX[NTOK*Dsz];
__device__ float g_T[NTOK*Dsz];
__device__ float g_FF[(size_t)NTOK*Fsz];
__device__ float g_SC[(size_t)Bsz*Hsz*Ssz*Ssz];
// transposed (tf32-rounded) weights
__device__ float g_WTq[(size_t)Lsz*Dsz*Dsz];
__device__ float g_WTk[(size_t)Lsz*Dsz*Dsz];
__device__ float g_WTv[(size_t)Lsz*Dsz*Dsz];
__device__ float g_WTo[(size_t)Lsz*Dsz*Dsz];
__device__ float g_WT1[(size_t)Lsz*Dsz*Fsz];
__device__ float g_WT2[(size_t)Lsz*Fsz*Dsz];
__device__ float g_WTout[(size_t)Vsz*Dsz];

__device__ __forceinline__ uint32_t smem_u32(const void* p) {
    uint32_t a;
    asm("{ .reg .u64 t; cvta.to.shared.u64 t, %1; cvt.u32.u64 %0, t; }" : "=r"(a) : "l"(p));
    return a;
}

// ================= weight transpose (+ tf32 rounding) =================
__global__ void transpose_tf32(const float* __restrict__ in, float* __restrict__ out,
                               int K, int N)
{
    __shared__ float tile[32][33];
    size_t off = (size_t)blockIdx.z * K * N;
    in += off; out += off;
    int tx = threadIdx.x, ty = threadIdx.y;
    int n = blockIdx.x * 32 + tx;
    int k0 = blockIdx.y * 32;
#pragma unroll
    for (int i = ty; i < 32; i += 8)
        tile[i][tx] = in[(size_t)(k0 + i) * N + n];
    __syncthreads();
    int k = k0 + tx;
    int n0 = blockIdx.x * 32;
#pragma unroll
    for (int i = ty; i < 32; i += 8) {
        float v = tile[tx][i];
        asm("cvt.rna.tf32.f32 %0, %0;" : "+f"(v));
        out[(size_t)(n0 + i) * K + k] = v;
    }
}

// ================= tf32 mma.sync GEMM: C = A[M,K] @ WT[N,K]^T + bias =================
// CTA 128x128, K chunk 32, 8 warps (2m x 4n), warp 64x32 of m16n8k8.
// Fragments via ldmatrix.x4 (tf32 8x4 tile == b16 8x8 tile). Pitch 36 floats:
// conflict-free for both float4 STS and LDSM (banks 4r+k cover 0..31 once).
#define GPAD 36
#define GEMM_SMEM (4*128*GPAD*4)

__device__ __forceinline__ void mma_tf32(float* d, const uint32_t* a, const uint32_t* b)
{
    asm volatile("mma.sync.aligned.m16n8k8.row.col.f32.tf32.tf32.f32 "
        "{%0,%1,%2,%3}, {%4,%5,%6,%7}, {%8,%9}, {%0,%1,%2,%3};"
        : "+f"(d[0]), "+f"(d[1]), "+f"(d[2]), "+f"(d[3])
        : "r"(a[0]), "r"(a[1]), "r"(a[2]), "r"(a[3]), "r"(b[0]), "r"(b[1]));
}

__device__ __forceinline__ void ldsm4(uint32_t* r, uint32_t addr)
{
    asm volatile("ldmatrix.sync.aligned.m8n8.x4.shared.b16 {%0,%1,%2,%3}, [%4];"
        : "=r"(r[0]), "=r"(r[1]), "=r"(r[2]), "=r"(r[3]) : "r"(addr));
}

__device__ __forceinline__ void gemm_mma_core(const float* __restrict__ A,
        const float* __restrict__ WT, const float* __restrict__ bias,
        float* __restrict__ C, int N, int K, int relu, int bx, int by)
{
    extern __shared__ float sm[];
    float* Abuf[2] = { sm,              sm + 2 * 128 * GPAD };
    float* Bbuf[2] = { sm + 128 * GPAD, sm + 3 * 128 * GPAD };

    int tid = threadIdx.x, lane = tid & 31, wid = tid >> 5;
    int m0 = (wid & 1) * 64;      // warp m-offset
    int n0 = (wid >> 1) * 32;     // warp n-offset

    const float* Ap = A  + (size_t)(by * 128) * K;
    const float* Bp = WT + (size_t)(bx * 128) * K;

    int gr = tid >> 3;            // 0..31 (stage row group)
    int gc = (tid & 7) * 4;       // 0..28 (stage col)

    // ldmatrix per-lane byte offsets (within a buffer), excl. mt/ntp/ks terms
    uint32_t aoff = ((uint32_t)(m0 + (lane & 15)) * GPAD + ((lane >> 4) << 2)) * 4u;
    uint32_t boff = ((uint32_t)(n0 + ((lane >> 4) << 3) + (lane & 7)) * GPAD
                     + (((lane >> 3) & 1) << 2)) * 4u;

    // ---- prologue: stage chunk 0 ----
    float4 av[4], bv[4];
#pragma unroll
    for (int i = 0; i < 4; i++) {
        av[i] = *(const float4*)(Ap + (size_t)(gr + 32 * i) * K + gc);
        bv[i] = *(const float4*)(Bp + (size_t)(gr + 32 * i) * K + gc);
        asm("cvt.rna.tf32.f32 %0, %0;" : "+f"(av[i].x));
        asm("cvt.rna.tf32.f32 %0, %0;" : "+f"(av[i].y));
        asm("cvt.rna.tf32.f32 %0, %0;" : "+f"(av[i].z));
        asm("cvt.rna.tf32.f32 %0, %0;" : "+f"(av[i].w));
    }
#pragma unroll
    for (int i = 0; i < 4; i++) {
        *(float4*)&Abuf[0][(gr + 32 * i) * GPAD + gc] = av[i];
        *(float4*)&Bbuf[0][(gr + 32 * i) * GPAD + gc] = bv[i];
    }
    __syncthreads();

    float acc[4][4][4] = {};
    int nch = K >> 5;
    for (int kt = 0; kt < nch; kt++) {
        int cur = kt & 1;
        if (kt + 1 < nch) {
            int k0 = (kt + 1) << 5;
#pragma unroll
            for (int i = 0; i < 4; i++) {
                av[i] = *(const float4*)(Ap + (size_t)(gr + 32 * i) * K + k0 + gc);
                bv[i] = *(const float4*)(Bp + (size_t)(gr + 32 * i) * K + k0 + gc);
                asm("cvt.rna.tf32.f32 %0, %0;" : "+f"(av[i].x));
                asm("cvt.rna.tf32.f32 %0, %0;" : "+f"(av[i].y));
                asm("cvt.rna.tf32.f32 %0, %0;" : "+f"(av[i].z));
                asm("cvt.rna.tf32.f32 %0, %0;" : "+f"(av[i].w));
            }
        }
        uint32_t aU = smem_u32(Abuf[cur]);
        uint32_t bU = smem_u32(Bbuf[cur]);
#pragma unroll
        for (int ks = 0; ks < 4; ks++) {
            uint32_t kbyte = (uint32_t)ks * 32u;   // 8 floats
            uint32_t bfr[2][4];
            ldsm4(bfr[0], bU + boff + kbyte);
            ldsm4(bfr[1], bU + boff + 16u * GPAD * 4u + kbyte);
#pragma unroll
            for (int mt = 0; mt < 4; mt++) {
                uint32_t afr[4];
                ldsm4(afr, aU + aoff + (uint32_t)mt * 16u * GPAD * 4u + kbyte);
#pragma unroll
                for (int nt = 0; nt < 4; nt++)
                    mma_tf32(acc[mt][nt], afr, &bfr[nt >> 1][(nt & 1) * 2]);
            }
        }
        if (kt + 1 < nch) {
            int nxt = cur ^ 1;
#pragma unroll
            for (int i = 0; i < 4; i++) {
                *(float4*)&Abuf[nxt][(gr + 32 * i) * GPAD + gc] = av[i];
                *(float4*)&Bbuf[nxt][(gr + 32 * i) * GPAD + gc] = bv[i];
            }
            __syncthreads();
        }
    }

    // epilogue
    int lg = lane >> 2, lt = lane & 3;
#pragma unroll
    for (int mt = 0; mt < 4; mt++) {
        int r1 = by * 128 + m0 + mt * 16 + lg;
#pragma unroll
        for (int nt = 0; nt < 4; nt++) {
            int cb = bx * 128 + n0 + nt * 8 + lt * 2;
            float2 bb = *(const float2*)(bias + cb);
            float2 v0, v1;
            v0.x = acc[mt][nt][0] + bb.x; v0.y = acc[mt][nt][1] + bb.y;
            v1.x = acc[mt][nt][2] + bb.x; v1.y = acc[mt][nt][3] + bb.y;
            if (relu) {
                v0.x = fmaxf(v0.x, 0.f); v0.y = fmaxf(v0.y, 0.f);
                v1.x = fmaxf(v1.x, 0.f); v1.y = fmaxf(v1.y, 0.f);
            }
            *(float2*)(C + (size_t)r1 * N + cb)       = v0;
            *(float2*)(C + (size_t)(r1 + 8) * N + cb) = v1;
        }
    }
}

__global__ __launch_bounds__(256, 2)
void gemm_mma(const float* __restrict__ A, const float* __restrict__ WT,
              const float* __restrict__ bias, float* __restrict__ C,
              int N, int K, int relu)
{
    gemm_mma_core(A, WT, bias, C, N, K, relu, blockIdx.y, blockIdx.x);
}

__global__ __launch_bounds__(256, 2)
void gemm_mma_qkv(const float* __restrict__ A,
                  const float* __restrict__ WTq, const float* __restrict__ bq, float* __restrict__ Q,
                  const float* __restrict__ WTk, const float* __restrict__ bk, float* __restrict__ Kp,
                  const float* __restrict__ WTv, const float* __restrict__ bv, float* __restrict__ V)
{
    const float* W = (blockIdx.z == 0) ? WTq : (blockIdx.z == 1) ? WTk : WTv;
    const float* b = (blockIdx.z == 0) ? bq  : (blockIdx.z == 1) ? bk  : bv;
    float* C       = (blockIdx.z == 0) ? Q   : (blockIdx.z == 1) ? Kp  : V;
    gemm_mma_core(A, W, b, C, Dsz, Dsz, 0, blockIdx.y, blockIdx.x);
}

// ---------------- embedding * sqrt(D) + sinusoidal PE ----------------
__global__ void embed_kernel(const int* __restrict__ ids, const float* __restrict__ emb,
                             float* __restrict__ X)
{
    int row = blockIdx.x;
    int s   = row % Ssz;
    int id  = ids[row];
    const float* e = emb + (size_t)id * Dsz;
    float* x = X + (size_t)row * Dsz;
    const float nl = -logf(10000.0f) / (float)Dsz;
    for (int d = threadIdx.x; d < Dsz; d += blockDim.x) {
        int i = d >> 1;
        float div = expf((float)(2 * i) * nl);
        float ang = (float)s * div;
        float pe  = (d & 1) ? cosf(ang) : sinf(ang);
        x[d] = e[d] * 32.0f + pe;
    }
}

// ---------------- attention scores ----------------
__global__ void attn_scores(const float* __restrict__ Q, const float* __restrict__ K,
                            const float* __restrict__ causal, const int* __restrict__ ids,
                            float* __restrict__ SC)
{
    int bh = blockIdx.z;
    int b = bh >> 4, h = bh & 15;
    int i0 = blockIdx.y * 64, j0 = blockIdx.x * 64;
    __shared__ float qs[HDsz][65];
    __shared__ float ks[HDsz][65];
    int tid = threadIdx.x, tx = tid & 15, ty = tid >> 4;
    const float* Qp = Q + ((size_t)(b * Ssz + i0)) * Dsz + h * HDsz;
    const float* Kp = K + ((size_t)(b * Ssz + j0)) * Dsz + h * HDsz;
#pragma unroll
    for (int i = tid; i < 64 * 64; i += 256) {
        int r = i >> 6, d = i & 63;
        qs[d][r] = Qp[(size_t)r * Dsz + d];
        ks[d][r] = Kp[(size_t)r * Dsz + d];
    }
    __syncthreads();
    float acc[4][4] = {};
#pragma unroll 8
    for (int d = 0; d < HDsz; d++) {
        float a[4], w[4];
#pragma unroll
        for (int i = 0; i < 4; i++) a[i] = qs[d][ty * 4 + i];
#pragma unroll
        for (int j = 0; j < 4; j++) w[j] = ks[d][tx * 4 + j];
#pragma unroll
        for (int i = 0; i < 4; i++)
#pragma unroll
            for (int j = 0; j < 4; j++)
                acc[i][j] = fmaf(a[i], w[j], acc[i][j]);
    }
    float* out = SC + (size_t)bh * Ssz * Ssz;
#pragma unroll
    for (int i = 0; i < 4; i++) {
        int ri = i0 + ty * 4 + i;
#pragma unroll
        for (int j = 0; j < 4; j++) {
            int cj = j0 + tx * 4 + j;
            float pad = (ids[b * Ssz + cj] == 0) ? NEG_INF : 0.0f;
            out[(size_t)ri * Ssz + cj] = acc[i][j] * 0.125f + causal[ri * Ssz + cj] + pad;
        }
    }
}

// ---------------- softmax over rows of length 512 ----------------
__global__ void softmax512(float* __restrict__ SC)
{
    float* p = SC + (size_t)blockIdx.x * Ssz;
    int t = threadIdx.x;
    float a = p[t], b2 = p[t + 256];
    __shared__ float red[256];
    red[t] = fmaxf(a, b2);
    __syncthreads();
    for (int s = 128; s > 0; s >>= 1) {
        if (t < s) red[t] = fmaxf(red[t], red[t + s]);
        __syncthreads();
    }
    float rmax = red[0];
    __syncthreads();
    if (rmax == NEG_INF) {
        p[t] = 1.0f / Ssz;
        p[t + 256] = 1.0f / Ssz;
        return;
    }
    float e0 = expf(a - rmax), e1 = expf(b2 - rmax);
    red[t] = e0 + e1;
    __syncthreads();
    for (int s = 128; s > 0; s >>= 1) {
        if (t < s) red[t] += red[t + s];
        __syncthreads();
    }
    float inv = 1.0f / red[0];
    p[t] = e0 * inv;
    p[t + 256] = e1 * inv;
}

// ---------------- ctx = softmax(scores) @ V ----------------
__global__ void attn_ctx(const float* __restrict__ SC, const float* __restrict__ V,
                         float* __restrict__ CTX)
{
    int bh = blockIdx.y;
    int b = bh >> 4, h = bh & 15;
    int i0 = blockIdx.x * 64;
    const float* W = SC + (size_t)bh * Ssz * Ssz;
    __shared__ float ws[16][65];
    __shared__ float vs[16][64];
    int tid = threadIdx.x, tx = tid & 15, ty = tid >> 4;
    float acc[4][4] = {};
    for (int j0 = 0; j0 < Ssz; j0 += 16) {
#pragma unroll
        for (int i = tid; i < 64 * 16; i += 256) {
            int r = i >> 4, c = i & 15;
            ws[c][r] = W[(size_t)(i0 + r) * Ssz + j0 + c];
        }
#pragma unroll
        for (int i = tid; i < 16 * 64; i += 256) {
            int c = i >> 6, n = i & 63;
            vs[c][n] = V[((size_t)(b * Ssz + j0 + c)) * Dsz + h * HDsz + n];
        }
        __syncthreads();
#pragma unroll
        for (int kk = 0; kk < 16; kk++) {
            float a[4], w[4];
#pragma unroll
            for (int i = 0; i < 4; i++) a[i] = ws[kk][ty * 4 + i];
#pragma unroll
            for (int j = 0; j < 4; j++) w[j] = vs[kk][tx * 4 + j];
#pragma unroll
            for (int i = 0; i < 4; i++)
#pragma unroll
                for (int j = 0; j < 4; j++)
                    acc[i][j] = fmaf(a[i], w[j], acc[i][j]);
        }
        __syncthreads();
    }
#pragma unroll
    for (int i = 0; i < 4; i++)
#pragma unroll
        for (int j = 0; j < 4; j++)
            CTX[((size_t)(b * Ssz + i0 + ty * 4 + i)) * Dsz + h * HDsz + tx * 4 + j] = acc[i][j];
}

// ---------------- X = LayerNorm(X + T) * g + b ----------------
__global__ void add_ln(const float* __restrict__ X, const float* __restrict__ T,
                       const float* __restrict__ g, const float* __restrict__ bb,
                       float* __restrict__ O)
{
    int row = blockIdx.x;
    int t = threadIdx.x;
    const float* x = X + (size_t)row * Dsz;
    const float* tt = T + (size_t)row * Dsz;
    float y[4];
    float s = 0.0f;
#pragma unroll
    for (int k = 0; k < 4; k++) {
        int d = t + k * 256;
        y[k] = x[d] + tt[d];
        s += y[k];
    }
    __shared__ float red[256];
    red[t] = s;
    __syncthreads();
    for (int st = 128; st > 0; st >>= 1) {
        if (t < st) red[t] += red[t + st];
        __syncthreads();
    }
    float mean = red[0] * (1.0f / Dsz);
    __syncthreads();
    float ss = 0.0f;
#pragma unroll
    for (int k = 0; k < 4; k++) {
        float d = y[k] - mean;
        ss += d * d;
    }
    red[t] = ss;
    __syncthreads();
    for (int st = 128; st > 0; st >>= 1) {
        if (t < st) red[t] += red[t + st];
        __syncthreads();
    }
    float var = red[0] * (1.0f / Dsz);
    float inv = rsqrtf(var + 1e-5f);
    float* o = O + (size_t)row * Dsz;
#pragma unroll
    for (int k = 0; k < 4; k++) {
        int d = t + k * 256;
        o[d] = (y[k] - mean) * inv * g[d] + bb[d];
    }
}

// ---------------- launch ----------------
extern "C" void kernel_launch(void* const* d_in, const int* in_sizes, int n_in,
                              void* d_out, int out_size)
{
    const int*   ids    = (const int*)  d_in[0];
    const float* causal = (const float*)d_in[1];
    const float* emb    = (const float*)d_in[2];
    const float* Wq     = (const float*)d_in[3];
    const float* bq     = (const float*)d_in[4];
    const float* Wk     = (const float*)d_in[5];
    const float* bk     = (const float*)d_in[6];
    const float* Wv     = (const float*)d_in[7];
    const float* bv     = (const float*)d_in[8];
    const float* Wo     = (const float*)d_in[9];
    const float* bo     = (const float*)d_in[10];
    const float* g1     = (const float*)d_in[11];
    const float* b1n    = (const float*)d_in[12];
    const float* W1     = (const float*)d_in[13];
    const float* b1f    = (const float*)d_in[14];
    const float* W2     = (const float*)d_in[15];
    const float* b2f    = (const float*)d_in[16];
    const float* g2     = (const float*)d_in[17];
    const float* b2n    = (const float*)d_in[18];
    const float* Wout   = (const float*)d_in[19];
    const float* bout   = (const float*)d_in[20];
    float* out = (float*)d_out;

    float *X, *Q, *K, *V, *CTX, *T, *FF, *SC;
    float *WTq, *WTk, *WTv, *WTo, *WT1, *WT2, *WTout;
    cudaGetSymbolAddress((void**)&X,   g_X);
    cudaGetSymbolAddress((void**)&Q,   g_Q);
    cudaGetSymbolAddress((void**)&K,   g_K);
    cudaGetSymbolAddress((void**)&V,   g_V);
    cudaGetSymbolAddress((void**)&CTX, g_CTX);
    cudaGetSymbolAddress((void**)&T,   g_T);
    cudaGetSymbolAddress((void**)&FF,  g_FF);
    cudaGetSymbolAddress((void**)&SC,  g_SC);
    cudaGetSymbolAddress((void**)&WTq, g_WTq);
    cudaGetSymbolAddress((void**)&WTk, g_WTk);
    cudaGetSymbolAddress((void**)&WTv, g_WTv);
    cudaGetSymbolAddress((void**)&WTo, g_WTo);
    cudaGetSymbolAddress((void**)&WT1, g_WT1);
    cudaGetSymbolAddress((void**)&WT2, g_WT2);
    cudaGetSymbolAddress((void**)&WTout, g_WTout);

    cudaFuncSetAttribute(gemm_mma,     cudaFuncAttributeMaxDynamicSharedMemorySize, GEMM_SMEM);
    cudaFuncSetAttribute(gemm_mma_qkv, cudaFuncAttributeMaxDynamicSharedMemorySize, GEMM_SMEM);

    // weight transposes (+tf32 rounding), recomputed every replay (deterministic)
    transpose_tf32<<<dim3(Dsz/32, Dsz/32, Lsz), dim3(32, 8)>>>(Wq, WTq, Dsz, Dsz);
    transpose_tf32<<<dim3(Dsz/32, Dsz/32, Lsz), dim3(32, 8)>>>(Wk, WTk, Dsz, Dsz);
    transpose_tf32<<<dim3(Dsz/32, Dsz/32, Lsz), dim3(32, 8)>>>(Wv, WTv, Dsz, Dsz);
    transpose_tf32<<<dim3(Dsz/32, Dsz/32, Lsz), dim3(32, 8)>>>(Wo, WTo, Dsz, Dsz);
    transpose_tf32<<<dim3(Fsz/32, Dsz/32, Lsz), dim3(32, 8)>>>(W1, WT1, Dsz, Fsz);
    transpose_tf32<<<dim3(Dsz/32, Fsz/32, Lsz), dim3(32, 8)>>>(W2, WT2, Fsz, Dsz);
    transpose_tf32<<<dim3(Vsz/32, Dsz/32, 1),   dim3(32, 8)>>>(Wout, WTout, Dsz, Vsz);

    embed_kernel<<<NTOK, 256>>>(ids, emb, X);

    for (int l = 0; l < Lsz; l++) {
        const float* wtq = WTq + (size_t)l * Dsz * Dsz;
        const float* wtk = WTk + (size_t)l * Dsz * Dsz;
        const float* wtv = WTv + (size_t)l * Dsz * Dsz;
        const float* wto = WTo + (size_t)l * Dsz * Dsz;
        const float* wt1 = WT1 + (size_t)l * Dsz * Fsz;
        const float* wt2 = WT2 + (size_t)l * Fsz * Dsz;
        const float* bql = bq + (size_t)l * Dsz;
        const float* bkl = bk + (size_t)l * Dsz;
        const float* bvl = bv + (size_t)l * Dsz;
        const float* bol = bo + (size_t)l * Dsz;
        const float* b1fl = b1f + (size_t)l * Fsz;
        const float* b2fl = b2f + (size_t)l * Dsz;
        const float* g1l = g1 + (size_t)l * Dsz;
        const float* b1nl = b1n + (size_t)l * Dsz;
        const float* g2l = g2 + (size_t)l * Dsz;
        const float* b2nl = b2n + (size_t)l * Dsz;

        gemm_mma_qkv<<<dim3(NTOK/128, Dsz/128, 3), 256, GEMM_SMEM>>>(
            X, wtq, bql, Q, wtk, bkl, K, wtv, bvl, V);

        attn_scores<<<dim3(Ssz/64, Ssz/64, Bsz*Hsz), 256>>>(Q, K, causal, ids, SC);
        softmax512<<<Bsz*Hsz*Ssz, 256>>>(SC);
        attn_ctx<<<dim3(Ssz/64, Bsz*Hsz), 256>>>(SC, V, CTX);

        gemm_mma<<<dim3(NTOK/128, Dsz/128), 256, GEMM_SMEM>>>(CTX, wto, bol, T, Dsz, Dsz, 0);
        add_ln<<<NTOK, 256>>>(X, T, g1l, b1nl, X);

        gemm_mma<<<dim3(NTOK/128, Fsz/128), 256, GEMM_SMEM>>>(X, wt1, b1fl, FF, Fsz, Dsz, 1);
        gemm_mma<<<dim3(NTOK/128, Dsz/128), 256, GEMM_SMEM>>>(FF, wt2, b2fl, T, Dsz, Fsz, 0);
        add_ln<<<NTOK, 256>>>(X, T, g2l, b2nl, X);
    }

    gemm_mma<<<dim3(NTOK/128, Vsz/128), 256, GEMM_SMEM>>>(X, WTout, bout, out, Vsz, Dsz, 0);
}